// round 13
// baseline (speedup 1.0000x reference)
#include <cuda_runtime.h>
#include <cuda_bf16.h>
#include <cstdint>

#define N_PTS 10000
#define DIM 64
#define NK4 (DIM / 4)                     // 16 packed k-steps
#define EPS 0.4f
#define BANDQ 0.07f                       // rigorous dp4a error bound ~0.064
#define INV_127SQ 6.2000124e-5f           // 1/16129
#define BM 128
#define NB ((N_PTS + BM - 1) / BM)        // 79
#define NTRI (NB * (NB + 1) / 2)          // 3160 upper-triangle blocks
#define ECAP (1 << 22)                    // 4M edge capacity (expect ~27K)
#define SM_EDGES 32768                    // edges cached in cc smem
#define WORDS ((N_PTS + 31) / 32)         // 313

// -------- static device scratch (no allocations allowed) --------
__device__ float    g_nf[N_PTS * DIM];    // normalized features, row-major (exact)
__device__ uint32_t g_qT[NK4 * N_PTS];    // int8x4-packed quantized, k-major [k4][p]
__device__ int      g_ecount;             // edge counter
__device__ int2     g_edges[ECAP];        // edge list (u < v)

// -------- 1) normalize rows + quantize-pack (transposed) -------------------
// 256 threads, 32 points/block. Warp computes 4 points; smem repack for the
// k-major int8x4 layout the pair kernel loads coalesced.
__global__ void __launch_bounds__(256) norm_init_kernel(const float* __restrict__ x) {
    __shared__ float sh[DIM][33];
    if (blockIdx.x == 0 && threadIdx.x == 0) g_ecount = 0;

    int p0 = blockIdx.x * 32;
    int warp = threadIdx.x >> 5;
    int lane = threadIdx.x & 31;

    #pragma unroll
    for (int q = 0; q < 4; q++) {
        int p = p0 + warp * 4 + q;
        float a = 0.f, b = 0.f;
        if (p < N_PTS) {
            a = x[p * DIM + lane];
            b = x[p * DIM + 32 + lane];
        }
        float ss = a * a + b * b;
        #pragma unroll
        for (int o = 16; o; o >>= 1) ss += __shfl_xor_sync(0xffffffffu, ss, o);
        float s = sqrtf(ss);              // IEEE sqrt + IEEE div (match reference)
        float va = a / s;
        float vb = b / s;
        if (p < N_PTS) {
            g_nf[p * DIM + lane]      = va;   // exact fp32 for recompute
            g_nf[p * DIM + 32 + lane] = vb;
        }
        sh[lane][warp * 4 + q]      = va;
        sh[lane + 32][warp * 4 + q] = vb;
    }
    __syncthreads();

    // pack 4 dims -> one int8x4 word; layout [k4][point] for coalesced loads
    for (int idx = threadIdx.x; idx < 32 * NK4; idx += 256) {
        int lp = idx & 31;
        int k4 = idx >> 5;
        int p = p0 + lp;
        if (p < N_PTS) {
            uint32_t w = 0;
            #pragma unroll
            for (int b = 0; b < 4; b++) {
                int v = (int)rintf(127.0f * sh[k4 * 4 + b][lp]);   // in [-127,127]
                w |= ((uint32_t)(uint8_t)(int8_t)v) << (b * 8);
            }
            g_qT[k4 * N_PTS + p] = w;
        }
    }
}

// -------- 2) dp4a-filtered pairwise similarity -> edge list ----------------
// 128x128 tile, 256 threads, 8x8 micro-tile (R9-proven mapping).
// int8x4 estimate with rigorous |err| <= 0.064: outside +-BANDQ of EPS the
// decision is provably identical to fp32; in-band -> exact fp32 recompute.
__global__ void __launch_bounds__(256) pair_edges_kernel() {
    // decode linear block -> (bi, bj), bi <= bj
    int L = blockIdx.x;
    float fb = (float)NB + 0.5f
             - sqrtf(((float)NB + 0.5f) * ((float)NB + 0.5f) - 2.0f * (float)L);
    int bi = (int)fb;
    if (bi > NB - 1) bi = NB - 1;
    if (bi < 0) bi = 0;
    while (bi > 0 && bi * NB - bi * (bi - 1) / 2 > L) bi--;
    while ((bi + 1) * NB - (bi + 1) * bi / 2 <= L) bi++;
    int bj = bi + (L - (bi * NB - bi * (bi - 1) / 2));

    __shared__ uint32_t Aq[NK4 * BM];   // [k4][m], 8 KB
    __shared__ uint32_t Bq[NK4 * BM];   // [k4][n], 8 KB

    int t = threadIdx.x;
    int i0 = bi * BM;
    int j0 = bj * BM;

    // tile loads: uint4 fast path (N_PTS % 4 == 0 -> rows 16B-aligned)
    {
        uint32_t* dst = Aq;
        int p0 = i0;
        #pragma unroll
        for (int s = 0; s < 2; s++) {
            if (p0 + BM <= N_PTS) {
                #pragma unroll
                for (int it = 0; it < 2; it++) {
                    int idx = it * 256 + t;        // uint4 index, 512 total
                    int k4 = idx >> 5;             // 32 uint4 per row
                    int m = idx & 31;
                    ((uint4*)dst)[idx] =
                        *(const uint4*)(g_qT + k4 * N_PTS + p0 + m * 4);
                }
            } else {
                #pragma unroll
                for (int it = 0; it < (NK4 * BM) / 256; it++) {
                    int idx = it * 256 + t;
                    int k4 = idx >> 7;
                    int m = idx & 127;
                    dst[idx] = (p0 + m < N_PTS) ? g_qT[k4 * N_PTS + p0 + m] : 0u;
                }
            }
            dst = Bq;
            p0 = j0;
        }
    }
    __syncthreads();

    int ty = t >> 4;   // 0..15 -> rows ty*4..+3 and +64
    int tx = t & 15;   // 0..15 -> cols tx*4..+3 and +64

    int acc[8][8];
    #pragma unroll
    for (int r = 0; r < 8; r++)
        #pragma unroll
        for (int c = 0; c < 8; c++) acc[r][c] = 0;

    #pragma unroll
    for (int k4 = 0; k4 < NK4; k4++) {
        const uint32_t* ak = Aq + k4 * BM;
        const uint32_t* bk = Bq + k4 * BM;
        uint4 a0 = *(const uint4*)(ak + ty * 4);
        uint4 a1 = *(const uint4*)(ak + ty * 4 + 64);
        uint4 b0 = *(const uint4*)(bk + tx * 4);
        uint4 b1 = *(const uint4*)(bk + tx * 4 + 64);

        int av[8] = {(int)a0.x, (int)a0.y, (int)a0.z, (int)a0.w,
                     (int)a1.x, (int)a1.y, (int)a1.z, (int)a1.w};
        int bv[8] = {(int)b0.x, (int)b0.y, (int)b0.z, (int)b0.w,
                     (int)b1.x, (int)b1.y, (int)b1.z, (int)b1.w};
        #pragma unroll
        for (int r = 0; r < 8; r++)
            #pragma unroll
            for (int c = 0; c < 8; c++)
                acc[r][c] = __dp4a(av[r], bv[c], acc[r][c]);
    }

    // emit edges: certain by estimate, or exact fp32 recompute in-band
    #pragma unroll
    for (int r = 0; r < 8; r++) {
        int gi = i0 + ty * 4 + (r & 3) + (r >> 2) * 64;
        #pragma unroll
        for (int c = 0; c < 8; c++) {
            int gj = j0 + tx * 4 + (c & 3) + (c >> 2) * 64;
            if (gj > gi && gj < N_PTS && gi < N_PTS) {
                float est = (float)acc[r][c] * INV_127SQ;
                bool edge;
                if (est > EPS + BANDQ) {
                    edge = true;
                } else if (est < EPS - BANDQ) {
                    edge = false;
                } else {
                    // exact sequential fp32 (k ascending), L2-resident data
                    const float4* pa = (const float4*)(g_nf + gi * DIM);
                    const float4* pb = (const float4*)(g_nf + gj * DIM);
                    float s = 0.0f;
                    #pragma unroll
                    for (int k = 0; k < DIM / 4; k++) {
                        float4 xa = pa[k];
                        float4 xb = pb[k];
                        s = fmaf(xa.x, xb.x, s);
                        s = fmaf(xa.y, xb.y, s);
                        s = fmaf(xa.z, xb.z, s);
                        s = fmaf(xa.w, xb.w, s);
                    }
                    edge = (s > EPS);
                }
                if (edge) {
                    int slot = atomicAdd(&g_ecount, 1);
                    if (slot < ECAP) g_edges[slot] = make_int2(gi, gj);
                }
            }
        }
    }
}

// -------- 3) fused CC + dense re-rank + float output (single block) --------
__global__ void __launch_bounds__(1024) cc_kernel(float* __restrict__ out) {
    extern __shared__ int dyn[];
    int* lab = dyn;               // [N_PTS]
    int* se  = dyn + N_PTS;       // [SM_EDGES] packed (u<<14 | v)
    __shared__ unsigned bitmap[WORDS];
    __shared__ int wpref[WORDS];
    __shared__ int changed;

    int t = threadIdx.x;
    for (int i = t; i < N_PTS; i += 1024) lab[i] = i;
    int m = g_ecount;
    if (m > ECAP) m = ECAP;
    int ms = m < SM_EDGES ? m : SM_EDGES;
    for (int e = t; e < ms; e += 1024) {
        int2 ed = g_edges[e];
        se[e] = (ed.x << 14) | ed.y;
    }
    __syncthreads();

    for (int iter = 0; iter < 64; iter++) {
        if (t == 0) changed = 0;
        __syncthreads();

        for (int e = t; e < ms; e += 1024) {
            int p = se[e];
            int u = p >> 14;
            int v = p & 16383;
            int a = lab[u];
            int b = lab[v];
            if (a < b) {
                if (atomicMin(&lab[v], a) > a) changed = 1;
            } else if (b < a) {
                if (atomicMin(&lab[u], b) > b) changed = 1;
            }
        }
        for (int e = SM_EDGES + t; e < m; e += 1024) {   // overflow tail
            int2 ed = g_edges[e];
            int a = lab[ed.x];
            int b = lab[ed.y];
            if (a < b) {
                if (atomicMin(&lab[ed.y], a) > a) changed = 1;
            } else if (b < a) {
                if (atomicMin(&lab[ed.x], b) > b) changed = 1;
            }
        }
        __syncthreads();

        #pragma unroll
        for (int j = 0; j < 3; j++) {
            for (int i = t; i < N_PTS; i += 1024) {
                int l = lab[i];
                int l2 = lab[l];
                if (l2 < l) { lab[i] = l2; changed = 1; }
            }
            __syncthreads();
        }

        int c = changed;
        __syncthreads();
        if (!c) break;
    }

    for (int w = t; w < WORDS; w += 1024) bitmap[w] = 0u;
    __syncthreads();
    for (int i = t; i < N_PTS; i += 1024)
        if (lab[i] == i) atomicOr(&bitmap[i >> 5], 1u << (i & 31));
    __syncthreads();

    if (t == 0) {
        int s = 0;
        for (int w = 0; w < WORDS; w++) { wpref[w] = s; s += __popc(bitmap[w]); }
    }
    __syncthreads();

    for (int i = t; i < N_PTS; i += 1024) {
        int l = lab[i];
        int rank = wpref[l >> 5] + __popc(bitmap[l >> 5] & ((1u << (l & 31)) - 1u));
        out[i] = (float)rank;
    }
}

extern "C" void kernel_launch(void* const* d_in, const int* in_sizes, int n_in,
                              void* d_out, int out_size) {
    const float* x = (const float*)d_in[0];
    float* out = (float*)d_out;

    const int cc_smem = (N_PTS + SM_EDGES) * sizeof(int);        // ~167 KB
    cudaFuncSetAttribute(cc_kernel,
                         cudaFuncAttributeMaxDynamicSharedMemorySize, cc_smem);

    norm_init_kernel<<<(N_PTS + 31) / 32, 256>>>(x);

    pair_edges_kernel<<<NTRI, 256>>>();

    cc_kernel<<<1, 1024, cc_smem>>>(out);
}

// round 15
// speedup vs baseline: 1.9791x; 1.9791x over previous
#include <cuda_runtime.h>
#include <cuda_bf16.h>
#include <cstdint>

#define N_PTS 10000
#define DIM 64
#define EPS 0.4f
#define BAND 1e-3f                        // >> rigorous split-bf16 err ~4e-5
#define BM 128
#define NB ((N_PTS + BM - 1) / BM)        // 79
#define NTRI (NB * (NB + 1) / 2)          // 3160 upper-triangle blocks
#define ECAP (1 << 22)                    // 4M edge capacity (expect ~27K)
#define SM_EDGES 32768                    // edges cached in cc smem
#define WORDS ((N_PTS + 31) / 32)         // 313

// smem byte offsets for the 4 bf16 tiles (each 128 rows x 64 halfs = 16 KB)
#define SMO_AH 0
#define SMO_AL 16384
#define SMO_BH 32768
#define SMO_BL 49152
#define SM_PAIR_TOTAL 65536

// -------- static device scratch (no allocations allowed) --------
__device__ float          g_nf[N_PTS * DIM];      // exact fp32, row-major
__device__ __nv_bfloat16  g_hi[N_PTS * DIM];      // bf16 high part, row-major
__device__ __nv_bfloat16  g_lo[N_PTS * DIM];      // bf16 low part,  row-major
__device__ int            g_ecount;
__device__ int2           g_edges[ECAP];

__device__ __forceinline__ uint32_t smem_u32(const void* p) {
    uint32_t a;
    asm("{ .reg .u64 t; cvta.to.shared.u64 t, %1; cvt.u32.u64 %0, t; }"
        : "=r"(a) : "l"(p));
    return a;
}

// -------- 1) normalize rows + bf16 hi/lo split (all row-major) -------------
__global__ void __launch_bounds__(256) norm_init_kernel(const float* __restrict__ x) {
    __shared__ float sh[DIM][33];
    if (blockIdx.x == 0 && threadIdx.x == 0) g_ecount = 0;

    int p0 = blockIdx.x * 32;
    int warp = threadIdx.x >> 5;
    int lane = threadIdx.x & 31;

    #pragma unroll
    for (int q = 0; q < 4; q++) {
        int p = p0 + warp * 4 + q;
        float a = 0.f, b = 0.f;
        if (p < N_PTS) {
            a = x[p * DIM + lane];
            b = x[p * DIM + 32 + lane];
        }
        float ss = a * a + b * b;
        #pragma unroll
        for (int o = 16; o; o >>= 1) ss += __shfl_xor_sync(0xffffffffu, ss, o);
        float s = sqrtf(ss);
        sh[lane][warp * 4 + q]      = (p < N_PTS) ? a / s : 0.f;
        sh[lane + 32][warp * 4 + q] = (p < N_PTS) ? b / s : 0.f;
    }
    __syncthreads();

    // row-major writes: fp32 exact + bf16 hi/lo split
    for (int idx = threadIdx.x; idx < 32 * DIM; idx += 256) {
        int lp = idx >> 6;          // local point
        int d  = idx & 63;
        int p = p0 + lp;
        if (p < N_PTS) {
            float v = sh[d][lp];
            __nv_bfloat16 vh = __float2bfloat16(v);
            __nv_bfloat16 vl = __float2bfloat16(v - __bfloat162float(vh));
            g_nf[p * DIM + d] = v;
            g_hi[p * DIM + d] = vh;
            g_lo[p * DIM + d] = vl;
        }
    }
}

// -------- 2) HMMA (mma.sync bf16) filtered pairwise -> edge list -----------
// est = hh + hl + lh in fp32 tensor-core accum; |est - fp32| <= ~4e-5.
// Outside EPS+-BAND the decision equals fp32's; in-band -> exact sequential
// fp32 recompute (bit-identical to the passing scalar pipeline).
__global__ void __launch_bounds__(256) pair_edges_kernel() {
    // decode linear block -> (bi, bj), bi <= bj
    int L = blockIdx.x;
    float fb = (float)NB + 0.5f
             - sqrtf(((float)NB + 0.5f) * ((float)NB + 0.5f) - 2.0f * (float)L);
    int bi = (int)fb;
    if (bi > NB - 1) bi = NB - 1;
    if (bi < 0) bi = 0;
    while (bi > 0 && bi * NB - bi * (bi - 1) / 2 > L) bi--;
    while ((bi + 1) * NB - (bi + 1) * bi / 2 <= L) bi++;
    int bj = bi + (L - (bi * NB - bi * (bi - 1) / 2));

    extern __shared__ char smem[];
    uint32_t sb = smem_u32(smem);
    int t = threadIdx.x;
    int i0 = bi * BM;
    int j0 = bj * BM;

    // ---- load 4 tiles (AH, AL from row i0; BH, BL from row j0) ------------
    // row-major 128 rows x 64 halfs (128 B/row); 16B chunks XOR-swizzled:
    // chunk' = chunk ^ (row & 7)  -> conflict-free LDSM later.
    {
        const __nv_bfloat16* srcs[4] = { g_hi, g_lo, g_hi, g_lo };
        const int offs[4] = { SMO_AH, SMO_AL, SMO_BH, SMO_BL };
        const int p0s[4] = { i0, i0, j0, j0 };
        #pragma unroll
        for (int mtx = 0; mtx < 4; mtx++) {
            char* dst = smem + offs[mtx];
            const __nv_bfloat16* src = srcs[mtx];
            int p0 = p0s[mtx];
            #pragma unroll
            for (int it = 0; it < 4; it++) {
                int idx = it * 256 + t;        // 1024 chunks (128 rows x 8)
                int row = idx >> 3;
                int ch  = idx & 7;
                uint4 v = make_uint4(0, 0, 0, 0);
                if (p0 + row < N_PTS)
                    v = *(const uint4*)(src + (p0 + row) * DIM + ch * 8);
                *(uint4*)(dst + row * 128 + ((ch ^ (row & 7)) << 4)) = v;
            }
        }
    }
    __syncthreads();

    // ---- warp decomposition: 2x4 warps, each warp 64(m) x 32(n) -----------
    int wid = t >> 5;
    int l = t & 31;
    int warp_m = wid >> 2;        // 0..1
    int warp_n = wid & 3;         // 0..3

    // A ldmatrix lane mapping (x4): m0 rows0-7/k0-7, m1 rows8-15/k0-7,
    // m2 rows0-7/k8-15, m3 rows8-15/k8-15 == {a0,a1,a2,a3} of m16n8k16
    int a_row_off = (l & 7) + ((l >> 3) & 1) * 8;   // within 16-row tile
    int a_cb = (l >> 4) & 1;                        // chunk bit (k halves)
    // B ldmatrix.x2 NON-trans on [n][k] rows: thread gets (n=l>>2, k=(l&3)*2)
    // == exactly the col-major B fragment. m0 = k0-7, m1 = k8-15.
    int lb = l & 15;
    int b_row_off = lb & 7;
    int b_cb = lb >> 3;

    float acc[4][4][4];           // [mi][ni][c0..c3]
    #pragma unroll
    for (int mi = 0; mi < 4; mi++)
        #pragma unroll
        for (int ni = 0; ni < 4; ni++)
            #pragma unroll
            for (int c = 0; c < 4; c++) acc[mi][ni][c] = 0.0f;

    const uint32_t abase[3] = { sb + SMO_AH, sb + SMO_AH, sb + SMO_AL };
    const uint32_t bbase[3] = { sb + SMO_BH, sb + SMO_BL, sb + SMO_BH };

    #pragma unroll
    for (int pass = 0; pass < 3; pass++) {
        uint32_t Ab = abase[pass];
        uint32_t Bb = bbase[pass];
        #pragma unroll
        for (int ks = 0; ks < 4; ks++) {
            // A fragments for the 4 m16 tiles
            uint32_t afr[4][4];
            #pragma unroll
            for (int mi = 0; mi < 4; mi++) {
                int row = warp_m * 64 + mi * 16 + a_row_off;
                uint32_t addr = Ab + row * 128
                              + (((2 * ks + a_cb) ^ (row & 7)) << 4);
                asm volatile(
                    "ldmatrix.sync.aligned.m8n8.x4.shared.b16 {%0,%1,%2,%3}, [%4];"
                    : "=r"(afr[mi][0]), "=r"(afr[mi][1]),
                      "=r"(afr[mi][2]), "=r"(afr[mi][3])
                    : "r"(addr));
            }
            // B fragments for the 4 n8 tiles (NON-trans: [n][k] rows)
            uint32_t bfr[4][2];
            #pragma unroll
            for (int ni = 0; ni < 4; ni++) {
                int row = warp_n * 32 + ni * 8 + b_row_off;
                uint32_t addr = Bb + row * 128
                              + (((2 * ks + b_cb) ^ (row & 7)) << 4);
                asm volatile(
                    "ldmatrix.sync.aligned.m8n8.x2.shared.b16 {%0,%1}, [%2];"
                    : "=r"(bfr[ni][0]), "=r"(bfr[ni][1])
                    : "r"(addr));
            }
            // 16 mma
            #pragma unroll
            for (int mi = 0; mi < 4; mi++)
                #pragma unroll
                for (int ni = 0; ni < 4; ni++)
                    asm volatile(
                        "mma.sync.aligned.m16n8k16.row.col.f32.bf16.bf16.f32 "
                        "{%0,%1,%2,%3}, {%4,%5,%6,%7}, {%8,%9}, {%0,%1,%2,%3};"
                        : "+f"(acc[mi][ni][0]), "+f"(acc[mi][ni][1]),
                          "+f"(acc[mi][ni][2]), "+f"(acc[mi][ni][3])
                        : "r"(afr[mi][0]), "r"(afr[mi][1]),
                          "r"(afr[mi][2]), "r"(afr[mi][3]),
                          "r"(bfr[ni][0]), "r"(bfr[ni][1]));
        }
    }

    // ---- epilogue: filter + band recompute + emit -------------------------
    int gid = l >> 2;     // groupID
    int tig = l & 3;
    #pragma unroll
    for (int mi = 0; mi < 4; mi++) {
        #pragma unroll
        for (int ni = 0; ni < 4; ni++) {
            #pragma unroll
            for (int c = 0; c < 4; c++) {
                int gi = i0 + warp_m * 64 + mi * 16 + gid + (c >> 1) * 8;
                int gj = j0 + warp_n * 32 + ni * 8 + tig * 2 + (c & 1);
                if (gj > gi && gj < N_PTS && gi < N_PTS) {
                    float est = acc[mi][ni][c];
                    bool edge;
                    if (est > EPS + BAND) {
                        edge = true;
                    } else if (est < EPS - BAND) {
                        edge = false;
                    } else {
                        const float4* pa = (const float4*)(g_nf + gi * DIM);
                        const float4* pb = (const float4*)(g_nf + gj * DIM);
                        float s = 0.0f;
                        #pragma unroll
                        for (int k = 0; k < DIM / 4; k++) {
                            float4 xa = pa[k];
                            float4 xb = pb[k];
                            s = fmaf(xa.x, xb.x, s);
                            s = fmaf(xa.y, xb.y, s);
                            s = fmaf(xa.z, xb.z, s);
                            s = fmaf(xa.w, xb.w, s);
                        }
                        edge = (s > EPS);
                    }
                    if (edge) {
                        int slot = atomicAdd(&g_ecount, 1);
                        if (slot < ECAP) g_edges[slot] = make_int2(gi, gj);
                    }
                }
            }
        }
    }
}

// -------- 3) fused CC + dense re-rank + float output (single block) --------
__global__ void __launch_bounds__(1024) cc_kernel(float* __restrict__ out) {
    extern __shared__ int dyn[];
    int* lab = dyn;               // [N_PTS]
    int* se  = dyn + N_PTS;       // [SM_EDGES] packed (u<<14 | v)
    __shared__ unsigned bitmap[WORDS];
    __shared__ int wpref[WORDS];
    __shared__ int changed;

    int t = threadIdx.x;
    for (int i = t; i < N_PTS; i += 1024) lab[i] = i;
    int m = g_ecount;
    if (m > ECAP) m = ECAP;
    int ms = m < SM_EDGES ? m : SM_EDGES;
    for (int e = t; e < ms; e += 1024) {
        int2 ed = g_edges[e];
        se[e] = (ed.x << 14) | ed.y;
    }
    __syncthreads();

    for (int iter = 0; iter < 64; iter++) {
        if (t == 0) changed = 0;
        __syncthreads();

        for (int e = t; e < ms; e += 1024) {
            int p = se[e];
            int u = p >> 14;
            int v = p & 16383;
            int a = lab[u];
            int b = lab[v];
            if (a < b) {
                if (atomicMin(&lab[v], a) > a) changed = 1;
            } else if (b < a) {
                if (atomicMin(&lab[u], b) > b) changed = 1;
            }
        }
        for (int e = SM_EDGES + t; e < m; e += 1024) {   // overflow tail
            int2 ed = g_edges[e];
            int a = lab[ed.x];
            int b = lab[ed.y];
            if (a < b) {
                if (atomicMin(&lab[ed.y], a) > a) changed = 1;
            } else if (b < a) {
                if (atomicMin(&lab[ed.x], b) > b) changed = 1;
            }
        }
        __syncthreads();

        #pragma unroll
        for (int j = 0; j < 3; j++) {
            for (int i = t; i < N_PTS; i += 1024) {
                int lv = lab[i];
                int l2 = lab[lv];
                if (l2 < lv) { lab[i] = l2; changed = 1; }
            }
            __syncthreads();
        }

        int c = changed;
        __syncthreads();
        if (!c) break;
    }

    for (int w = t; w < WORDS; w += 1024) bitmap[w] = 0u;
    __syncthreads();
    for (int i = t; i < N_PTS; i += 1024)
        if (lab[i] == i) atomicOr(&bitmap[i >> 5], 1u << (i & 31));
    __syncthreads();

    if (t == 0) {
        int s = 0;
        for (int w = 0; w < WORDS; w++) { wpref[w] = s; s += __popc(bitmap[w]); }
    }
    __syncthreads();

    for (int i = t; i < N_PTS; i += 1024) {
        int lv = lab[i];
        int rank = wpref[lv >> 5] + __popc(bitmap[lv >> 5] & ((1u << (lv & 31)) - 1u));
        out[i] = (float)rank;
    }
}

extern "C" void kernel_launch(void* const* d_in, const int* in_sizes, int n_in,
                              void* d_out, int out_size) {
    const float* x = (const float*)d_in[0];
    float* out = (float*)d_out;

    const int cc_smem = (N_PTS + SM_EDGES) * sizeof(int);        // ~167 KB
    cudaFuncSetAttribute(pair_edges_kernel,
                         cudaFuncAttributeMaxDynamicSharedMemorySize, SM_PAIR_TOTAL);
    cudaFuncSetAttribute(cc_kernel,
                         cudaFuncAttributeMaxDynamicSharedMemorySize, cc_smem);

    norm_init_kernel<<<(N_PTS + 31) / 32, 256>>>(x);

    pair_edges_kernel<<<NTRI, 256, SM_PAIR_TOTAL>>>();

    cc_kernel<<<1, 1024, cc_smem>>>(out);
}

// round 16
// speedup vs baseline: 2.9687x; 1.5000x over previous
#include <cuda_runtime.h>
#include <cuda_bf16.h>
#include <cstdint>

#define N_PTS 10000
#define DIM 64
#define EPS 0.4f
#define BANDQ 0.006f                      // rigorous hh-only bf16 bound 0.0039
#define BM 128
#define NB ((N_PTS + BM - 1) / BM)        // 79
#define NTRI (NB * (NB + 1) / 2)          // 3160 upper-triangle blocks
#define ECAP (1 << 22)                    // 4M edge capacity (expect ~27K)
#define SM_EDGES 32768                    // edges cached in cc smem
#define WORDS ((N_PTS + 31) / 32)         // 313

// smem: 2 bf16 tiles (128 rows x 64 halfs = 16 KB each)
#define SMO_A 0
#define SMO_B 16384
#define SM_PAIR_TOTAL 32768

// -------- static device scratch (no allocations allowed) --------
__device__ float          g_nf[N_PTS * DIM];      // exact fp32, row-major
__device__ __nv_bfloat16  g_hi[N_PTS * DIM];      // bf16 rounded, row-major
__device__ int            g_ecount;
__device__ int2           g_edges[ECAP];

__device__ __forceinline__ uint32_t smem_u32(const void* p) {
    uint32_t a;
    asm("{ .reg .u64 t; cvta.to.shared.u64 t, %1; cvt.u32.u64 %0, t; }"
        : "=r"(a) : "l"(p));
    return a;
}

// -------- 1) normalize rows + bf16 round (row-major) -----------------------
__global__ void __launch_bounds__(256) norm_init_kernel(const float* __restrict__ x) {
    __shared__ float sh[DIM][33];
    if (blockIdx.x == 0 && threadIdx.x == 0) g_ecount = 0;

    int p0 = blockIdx.x * 32;
    int warp = threadIdx.x >> 5;
    int lane = threadIdx.x & 31;

    #pragma unroll
    for (int q = 0; q < 4; q++) {
        int p = p0 + warp * 4 + q;
        float a = 0.f, b = 0.f;
        if (p < N_PTS) {
            a = x[p * DIM + lane];
            b = x[p * DIM + 32 + lane];
        }
        float ss = a * a + b * b;
        #pragma unroll
        for (int o = 16; o; o >>= 1) ss += __shfl_xor_sync(0xffffffffu, ss, o);
        float s = sqrtf(ss);
        sh[lane][warp * 4 + q]      = (p < N_PTS) ? a / s : 0.f;
        sh[lane + 32][warp * 4 + q] = (p < N_PTS) ? b / s : 0.f;
    }
    __syncthreads();

    for (int idx = threadIdx.x; idx < 32 * DIM; idx += 256) {
        int lp = idx >> 6;          // local point
        int d  = idx & 63;
        int p = p0 + lp;
        if (p < N_PTS) {
            float v = sh[d][lp];
            g_nf[p * DIM + d] = v;
            g_hi[p * DIM + d] = __float2bfloat16(v);
        }
    }
}

// -------- 2) HMMA (bf16, single pass) filtered pairwise -> edge list -------
// est = sum bf16(a)*bf16(b) in fp32 tensor accum; rigorous |est-fp32|<=0.004.
// Outside EPS+-BANDQ the decision equals fp32's; in-band (~9.5K pairs chip-
// wide) -> exact sequential fp32 recompute (bit-identical labels).
__global__ void __launch_bounds__(256) pair_edges_kernel() {
    // decode linear block -> (bi, bj), bi <= bj
    int L = blockIdx.x;
    float fb = (float)NB + 0.5f
             - sqrtf(((float)NB + 0.5f) * ((float)NB + 0.5f) - 2.0f * (float)L);
    int bi = (int)fb;
    if (bi > NB - 1) bi = NB - 1;
    if (bi < 0) bi = 0;
    while (bi > 0 && bi * NB - bi * (bi - 1) / 2 > L) bi--;
    while ((bi + 1) * NB - (bi + 1) * bi / 2 <= L) bi++;
    int bj = bi + (L - (bi * NB - bi * (bi - 1) / 2));

    extern __shared__ char smem[];
    uint32_t sb = smem_u32(smem);
    int t = threadIdx.x;
    int i0 = bi * BM;
    int j0 = bj * BM;

    // ---- load A,B hi tiles; 16B chunks XOR-swizzled (ch ^ row&7) ----------
    {
        const int offs[2] = { SMO_A, SMO_B };
        const int p0s[2] = { i0, j0 };
        #pragma unroll
        for (int mtx = 0; mtx < 2; mtx++) {
            char* dst = smem + offs[mtx];
            int p0 = p0s[mtx];
            #pragma unroll
            for (int it = 0; it < 4; it++) {
                int idx = it * 256 + t;        // 1024 chunks (128 rows x 8)
                int row = idx >> 3;
                int ch  = idx & 7;
                uint4 v = make_uint4(0, 0, 0, 0);
                if (p0 + row < N_PTS)
                    v = *(const uint4*)(g_hi + (p0 + row) * DIM + ch * 8);
                *(uint4*)(dst + row * 128 + ((ch ^ (row & 7)) << 4)) = v;
            }
        }
    }
    __syncthreads();

    // ---- warp decomposition: 2x4 warps, each warp 64(m) x 32(n) -----------
    int wid = t >> 5;
    int l = t & 31;
    int warp_m = wid >> 2;        // 0..1
    int warp_n = wid & 3;         // 0..3

    // shared x4 lane mapping (A and B identical): lanes 0-7 -> (rows+0,ck0),
    // 8-15 -> (rows+8,ck0), 16-23 -> (rows+0,ck1), 24-31 -> (rows+8,ck1)
    int row_off = (l & 7) + ((l >> 3) & 1) * 8;
    int cb = (l >> 4) & 1;

    float acc[4][4][4];           // [mi][ni][c0..c3]
    #pragma unroll
    for (int mi = 0; mi < 4; mi++)
        #pragma unroll
        for (int ni = 0; ni < 4; ni++)
            #pragma unroll
            for (int c = 0; c < 4; c++) acc[mi][ni][c] = 0.0f;

    uint32_t Ab = sb + SMO_A;
    uint32_t Bb = sb + SMO_B;

    #pragma unroll
    for (int ks = 0; ks < 4; ks++) {
        // A fragments: 4 m16-tiles via ldmatrix.x4
        uint32_t afr[4][4];
        #pragma unroll
        for (int mi = 0; mi < 4; mi++) {
            int row = warp_m * 64 + mi * 16 + row_off;
            uint32_t addr = Ab + row * 128 + (((2 * ks + cb) ^ (row & 7)) << 4);
            asm volatile(
                "ldmatrix.sync.aligned.m8n8.x4.shared.b16 {%0,%1,%2,%3}, [%4];"
                : "=r"(afr[mi][0]), "=r"(afr[mi][1]),
                  "=r"(afr[mi][2]), "=r"(afr[mi][3])
                : "r"(addr));
        }
        // B fragments: 2 x ldmatrix.x4 cover 4 n8-tiles
        // regs: r0=(n+0..7,ck0) r1=(n+8..15,ck0) r2=(n+0..7,ck1) r3=(n+8..15,ck1)
        uint32_t bfr[4][2];
        #pragma unroll
        for (int nt = 0; nt < 2; nt++) {
            int row = warp_n * 32 + nt * 16 + row_off;
            uint32_t addr = Bb + row * 128 + (((2 * ks + cb) ^ (row & 7)) << 4);
            uint32_t r0, r1, r2, r3;
            asm volatile(
                "ldmatrix.sync.aligned.m8n8.x4.shared.b16 {%0,%1,%2,%3}, [%4];"
                : "=r"(r0), "=r"(r1), "=r"(r2), "=r"(r3)
                : "r"(addr));
            bfr[nt * 2 + 0][0] = r0; bfr[nt * 2 + 0][1] = r2;
            bfr[nt * 2 + 1][0] = r1; bfr[nt * 2 + 1][1] = r3;
        }
        // 16 mma
        #pragma unroll
        for (int mi = 0; mi < 4; mi++)
            #pragma unroll
            for (int ni = 0; ni < 4; ni++)
                asm volatile(
                    "mma.sync.aligned.m16n8k16.row.col.f32.bf16.bf16.f32 "
                    "{%0,%1,%2,%3}, {%4,%5,%6,%7}, {%8,%9}, {%0,%1,%2,%3};"
                    : "+f"(acc[mi][ni][0]), "+f"(acc[mi][ni][1]),
                      "+f"(acc[mi][ni][2]), "+f"(acc[mi][ni][3])
                    : "r"(afr[mi][0]), "r"(afr[mi][1]),
                      "r"(afr[mi][2]), "r"(afr[mi][3]),
                      "r"(bfr[ni][0]), "r"(bfr[ni][1]));
    }

    // ---- epilogue: filter + band recompute + emit -------------------------
    int gid = l >> 2;     // groupID
    int tig = l & 3;
    #pragma unroll
    for (int mi = 0; mi < 4; mi++) {
        #pragma unroll
        for (int ni = 0; ni < 4; ni++) {
            #pragma unroll
            for (int c = 0; c < 4; c++) {
                int gi = i0 + warp_m * 64 + mi * 16 + gid + (c >> 1) * 8;
                int gj = j0 + warp_n * 32 + ni * 8 + tig * 2 + (c & 1);
                if (gj > gi && gj < N_PTS && gi < N_PTS) {
                    float est = acc[mi][ni][c];
                    bool edge;
                    if (est > EPS + BANDQ) {
                        edge = true;
                    } else if (est < EPS - BANDQ) {
                        edge = false;
                    } else {
                        const float4* pa = (const float4*)(g_nf + gi * DIM);
                        const float4* pb = (const float4*)(g_nf + gj * DIM);
                        float s = 0.0f;
                        #pragma unroll
                        for (int k = 0; k < DIM / 4; k++) {
                            float4 xa = pa[k];
                            float4 xb = pb[k];
                            s = fmaf(xa.x, xb.x, s);
                            s = fmaf(xa.y, xb.y, s);
                            s = fmaf(xa.z, xb.z, s);
                            s = fmaf(xa.w, xb.w, s);
                        }
                        edge = (s > EPS);
                    }
                    if (edge) {
                        int slot = atomicAdd(&g_ecount, 1);
                        if (slot < ECAP) g_edges[slot] = make_int2(gi, gj);
                    }
                }
            }
        }
    }
}

// -------- 3) fused CC + dense re-rank + float output (single block) --------
__global__ void __launch_bounds__(1024) cc_kernel(float* __restrict__ out) {
    extern __shared__ int dyn[];
    int* lab = dyn;               // [N_PTS]
    int* se  = dyn + N_PTS;       // [SM_EDGES] packed (u<<14 | v)
    __shared__ unsigned bitmap[WORDS];
    __shared__ int wpref[WORDS];
    __shared__ int changed;

    int t = threadIdx.x;
    for (int i = t; i < N_PTS; i += 1024) lab[i] = i;
    int m = g_ecount;
    if (m > ECAP) m = ECAP;
    int ms = m < SM_EDGES ? m : SM_EDGES;
    for (int e = t; e < ms; e += 1024) {
        int2 ed = g_edges[e];
        se[e] = (ed.x << 14) | ed.y;
    }
    __syncthreads();

    for (int iter = 0; iter < 64; iter++) {
        if (t == 0) changed = 0;
        __syncthreads();

        for (int e = t; e < ms; e += 1024) {
            int p = se[e];
            int u = p >> 14;
            int v = p & 16383;
            int a = lab[u];
            int b = lab[v];
            if (a < b) {
                if (atomicMin(&lab[v], a) > a) changed = 1;
            } else if (b < a) {
                if (atomicMin(&lab[u], b) > b) changed = 1;
            }
        }
        for (int e = SM_EDGES + t; e < m; e += 1024) {   // overflow tail
            int2 ed = g_edges[e];
            int a = lab[ed.x];
            int b = lab[ed.y];
            if (a < b) {
                if (atomicMin(&lab[ed.y], a) > a) changed = 1;
            } else if (b < a) {
                if (atomicMin(&lab[ed.x], b) > b) changed = 1;
            }
        }
        __syncthreads();

        #pragma unroll
        for (int j = 0; j < 3; j++) {
            for (int i = t; i < N_PTS; i += 1024) {
                int lv = lab[i];
                int l2 = lab[lv];
                if (l2 < lv) { lab[i] = l2; changed = 1; }
            }
            __syncthreads();
        }

        int c = changed;
        __syncthreads();
        if (!c) break;
    }

    for (int w = t; w < WORDS; w += 1024) bitmap[w] = 0u;
    __syncthreads();
    for (int i = t; i < N_PTS; i += 1024)
        if (lab[i] == i) atomicOr(&bitmap[i >> 5], 1u << (i & 31));
    __syncthreads();

    if (t == 0) {
        int s = 0;
        for (int w = 0; w < WORDS; w++) { wpref[w] = s; s += __popc(bitmap[w]); }
    }
    __syncthreads();

    for (int i = t; i < N_PTS; i += 1024) {
        int lv = lab[i];
        int rank = wpref[lv >> 5] + __popc(bitmap[lv >> 5] & ((1u << (lv & 31)) - 1u));
        out[i] = (float)rank;
    }
}

extern "C" void kernel_launch(void* const* d_in, const int* in_sizes, int n_in,
                              void* d_out, int out_size) {
    const float* x = (const float*)d_in[0];
    float* out = (float*)d_out;

    const int cc_smem = (N_PTS + SM_EDGES) * sizeof(int);        // ~167 KB
    cudaFuncSetAttribute(pair_edges_kernel,
                         cudaFuncAttributeMaxDynamicSharedMemorySize, SM_PAIR_TOTAL);
    cudaFuncSetAttribute(cc_kernel,
                         cudaFuncAttributeMaxDynamicSharedMemorySize, cc_smem);

    norm_init_kernel<<<(N_PTS + 31) / 32, 256>>>(x);

    pair_edges_kernel<<<NTRI, 256, SM_PAIR_TOTAL>>>();

    cc_kernel<<<1, 1024, cc_smem>>>(out);
}

// round 17
// speedup vs baseline: 3.2874x; 1.1074x over previous
#include <cuda_runtime.h>
#include <cuda_bf16.h>
#include <cstdint>

#define N_PTS 10000
#define DIM 64
#define EPS 0.4f
#define BANDQ 0.006f                      // rigorous hh-only bf16 bound 0.0039
#define BM 128
#define NB ((N_PTS + BM - 1) / BM)        // 79
#define NTRI (NB * (NB + 1) / 2)          // 3160 upper-triangle blocks
#define ECAP (1 << 22)                    // 4M edge capacity (expect ~27K)
#define SM_EDGES 32768                    // edges cached in cc smem
#define WORDS ((N_PTS + 31) / 32)         // 313

// smem: 2 bf16 tiles (128 rows x 64 halfs = 16 KB each)
#define SMO_A 0
#define SMO_B 16384
#define SM_PAIR_TOTAL 32768

// -------- static device scratch (no allocations allowed) --------
__device__ float          g_nf[N_PTS * DIM];      // exact fp32, row-major
__device__ __nv_bfloat16  g_hi[N_PTS * DIM];      // bf16 rounded, row-major
__device__ int            g_ecount;
__device__ int2           g_edges[ECAP];

__device__ __forceinline__ uint32_t smem_u32(const void* p) {
    uint32_t a;
    asm("{ .reg .u64 t; cvta.to.shared.u64 t, %1; cvt.u32.u64 %0, t; }"
        : "=r"(a) : "l"(p));
    return a;
}

// -------- 1) normalize rows + bf16 round (row-major) -----------------------
__global__ void __launch_bounds__(256) norm_init_kernel(const float* __restrict__ x) {
    __shared__ float sh[DIM][33];
    if (blockIdx.x == 0 && threadIdx.x == 0) g_ecount = 0;

    int p0 = blockIdx.x * 32;
    int warp = threadIdx.x >> 5;
    int lane = threadIdx.x & 31;

    #pragma unroll
    for (int q = 0; q < 4; q++) {
        int p = p0 + warp * 4 + q;
        float a = 0.f, b = 0.f;
        if (p < N_PTS) {
            a = x[p * DIM + lane];
            b = x[p * DIM + 32 + lane];
        }
        float ss = a * a + b * b;
        #pragma unroll
        for (int o = 16; o; o >>= 1) ss += __shfl_xor_sync(0xffffffffu, ss, o);
        float s = sqrtf(ss);
        sh[lane][warp * 4 + q]      = (p < N_PTS) ? a / s : 0.f;
        sh[lane + 32][warp * 4 + q] = (p < N_PTS) ? b / s : 0.f;
    }
    __syncthreads();

    for (int idx = threadIdx.x; idx < 32 * DIM; idx += 256) {
        int lp = idx >> 6;          // local point
        int d  = idx & 63;
        int p = p0 + lp;
        if (p < N_PTS) {
            float v = sh[d][lp];
            g_nf[p * DIM + d] = v;
            g_hi[p * DIM + d] = __float2bfloat16(v);
        }
    }
}

// -------- 2) HMMA (bf16, single pass) filtered pairwise -> edge list -------
// est = sum bf16(a)*bf16(b) in fp32 tensor accum; rigorous |est-fp32|<=0.004.
// Outside EPS+-BANDQ the decision equals fp32's; in-band -> exact sequential
// fp32 recompute. Epilogue: per-mma-tile max reject skips 99.7% of groups.
__global__ void __launch_bounds__(256) pair_edges_kernel() {
    // decode linear block -> (bi, bj), bi <= bj
    int L = blockIdx.x;
    float fb = (float)NB + 0.5f
             - sqrtf(((float)NB + 0.5f) * ((float)NB + 0.5f) - 2.0f * (float)L);
    int bi = (int)fb;
    if (bi > NB - 1) bi = NB - 1;
    if (bi < 0) bi = 0;
    while (bi > 0 && bi * NB - bi * (bi - 1) / 2 > L) bi--;
    while ((bi + 1) * NB - (bi + 1) * bi / 2 <= L) bi++;
    int bj = bi + (L - (bi * NB - bi * (bi - 1) / 2));

    extern __shared__ char smem[];
    uint32_t sb = smem_u32(smem);
    int t = threadIdx.x;
    int i0 = bi * BM;
    int j0 = bj * BM;

    // ---- load A,B hi tiles; 16B chunks XOR-swizzled (ch ^ row&7) ----------
    {
        const int offs[2] = { SMO_A, SMO_B };
        const int p0s[2] = { i0, j0 };
        #pragma unroll
        for (int mtx = 0; mtx < 2; mtx++) {
            char* dst = smem + offs[mtx];
            int p0 = p0s[mtx];
            #pragma unroll
            for (int it = 0; it < 4; it++) {
                int idx = it * 256 + t;        // 1024 chunks (128 rows x 8)
                int row = idx >> 3;
                int ch  = idx & 7;
                uint4 v = make_uint4(0, 0, 0, 0);
                if (p0 + row < N_PTS)
                    v = *(const uint4*)(g_hi + (p0 + row) * DIM + ch * 8);
                *(uint4*)(dst + row * 128 + ((ch ^ (row & 7)) << 4)) = v;
            }
        }
    }
    __syncthreads();

    // ---- warp decomposition: 2x4 warps, each warp 64(m) x 32(n) -----------
    int wid = t >> 5;
    int l = t & 31;
    int warp_m = wid >> 2;        // 0..1
    int warp_n = wid & 3;         // 0..3

    int row_off = (l & 7) + ((l >> 3) & 1) * 8;
    int cb = (l >> 4) & 1;

    float acc[4][4][4];           // [mi][ni][c0..c3]
    #pragma unroll
    for (int mi = 0; mi < 4; mi++)
        #pragma unroll
        for (int ni = 0; ni < 4; ni++)
            #pragma unroll
            for (int c = 0; c < 4; c++) acc[mi][ni][c] = 0.0f;

    uint32_t Ab = sb + SMO_A;
    uint32_t Bb = sb + SMO_B;

    #pragma unroll
    for (int ks = 0; ks < 4; ks++) {
        uint32_t afr[4][4];
        #pragma unroll
        for (int mi = 0; mi < 4; mi++) {
            int row = warp_m * 64 + mi * 16 + row_off;
            uint32_t addr = Ab + row * 128 + (((2 * ks + cb) ^ (row & 7)) << 4);
            asm volatile(
                "ldmatrix.sync.aligned.m8n8.x4.shared.b16 {%0,%1,%2,%3}, [%4];"
                : "=r"(afr[mi][0]), "=r"(afr[mi][1]),
                  "=r"(afr[mi][2]), "=r"(afr[mi][3])
                : "r"(addr));
        }
        uint32_t bfr[4][2];
        #pragma unroll
        for (int nt = 0; nt < 2; nt++) {
            int row = warp_n * 32 + nt * 16 + row_off;
            uint32_t addr = Bb + row * 128 + (((2 * ks + cb) ^ (row & 7)) << 4);
            uint32_t r0, r1, r2, r3;
            asm volatile(
                "ldmatrix.sync.aligned.m8n8.x4.shared.b16 {%0,%1,%2,%3}, [%4];"
                : "=r"(r0), "=r"(r1), "=r"(r2), "=r"(r3)
                : "r"(addr));
            bfr[nt * 2 + 0][0] = r0; bfr[nt * 2 + 0][1] = r2;
            bfr[nt * 2 + 1][0] = r1; bfr[nt * 2 + 1][1] = r3;
        }
        #pragma unroll
        for (int mi = 0; mi < 4; mi++)
            #pragma unroll
            for (int ni = 0; ni < 4; ni++)
                asm volatile(
                    "mma.sync.aligned.m16n8k16.row.col.f32.bf16.bf16.f32 "
                    "{%0,%1,%2,%3}, {%4,%5,%6,%7}, {%8,%9}, {%0,%1,%2,%3};"
                    : "+f"(acc[mi][ni][0]), "+f"(acc[mi][ni][1]),
                      "+f"(acc[mi][ni][2]), "+f"(acc[mi][ni][3])
                    : "r"(afr[mi][0]), "r"(afr[mi][1]),
                      "r"(afr[mi][2]), "r"(afr[mi][3]),
                      "r"(bfr[ni][0]), "r"(bfr[ni][1]));
    }

    // ---- epilogue: group max-reject, then rare exact handling -------------
    int gid = l >> 2;     // groupID
    int tig = l & 3;
    #pragma unroll
    for (int mi = 0; mi < 4; mi++) {
        #pragma unroll
        for (int ni = 0; ni < 4; ni++) {
            const float* a4 = acc[mi][ni];
            float mx = fmaxf(fmaxf(a4[0], a4[1]), fmaxf(a4[2], a4[3]));
            if (mx > EPS - BANDQ) {            // ~0.3% of groups
                #pragma unroll
                for (int c = 0; c < 4; c++) {
                    int gi = i0 + warp_m * 64 + mi * 16 + gid + (c >> 1) * 8;
                    int gj = j0 + warp_n * 32 + ni * 8 + tig * 2 + (c & 1);
                    if (gj > gi && gj < N_PTS && gi < N_PTS) {
                        float est = a4[c];
                        bool edge;
                        if (est > EPS + BANDQ) {
                            edge = true;
                        } else if (est < EPS - BANDQ) {
                            edge = false;
                        } else {
                            const float4* pa = (const float4*)(g_nf + gi * DIM);
                            const float4* pb = (const float4*)(g_nf + gj * DIM);
                            float s = 0.0f;
                            #pragma unroll
                            for (int k = 0; k < DIM / 4; k++) {
                                float4 xa = pa[k];
                                float4 xb = pb[k];
                                s = fmaf(xa.x, xb.x, s);
                                s = fmaf(xa.y, xb.y, s);
                                s = fmaf(xa.z, xb.z, s);
                                s = fmaf(xa.w, xb.w, s);
                            }
                            edge = (s > EPS);
                        }
                        if (edge) {
                            int slot = atomicAdd(&g_ecount, 1);
                            if (slot < ECAP) g_edges[slot] = make_int2(gi, gj);
                        }
                    }
                }
            }
        }
    }
}

// -------- 3) fused CC + dense re-rank + float output (single block) --------
__global__ void __launch_bounds__(1024) cc_kernel(float* __restrict__ out) {
    extern __shared__ int dyn[];
    int* lab = dyn;               // [N_PTS]
    int* se  = dyn + N_PTS;       // [SM_EDGES] packed (u<<14 | v)
    __shared__ unsigned bitmap[WORDS];
    __shared__ int wpref[WORDS];
    __shared__ int changed;

    int t = threadIdx.x;
    for (int i = t; i < N_PTS; i += 1024) lab[i] = i;
    int m = g_ecount;
    if (m > ECAP) m = ECAP;
    int ms = m < SM_EDGES ? m : SM_EDGES;
    for (int e = t; e < ms; e += 1024) {
        int2 ed = g_edges[e];
        se[e] = (ed.x << 14) | ed.y;
    }
    __syncthreads();

    for (int iter = 0; iter < 64; iter++) {
        if (t == 0) changed = 0;
        __syncthreads();

        for (int e = t; e < ms; e += 1024) {
            int p = se[e];
            int u = p >> 14;
            int v = p & 16383;
            int a = lab[u];
            int b = lab[v];
            if (a < b) {
                if (atomicMin(&lab[v], a) > a) changed = 1;
            } else if (b < a) {
                if (atomicMin(&lab[u], b) > b) changed = 1;
            }
        }
        for (int e = SM_EDGES + t; e < m; e += 1024) {   // overflow tail
            int2 ed = g_edges[e];
            int a = lab[ed.x];
            int b = lab[ed.y];
            if (a < b) {
                if (atomicMin(&lab[ed.y], a) > a) changed = 1;
            } else if (b < a) {
                if (atomicMin(&lab[ed.x], b) > b) changed = 1;
            }
        }
        __syncthreads();

        #pragma unroll
        for (int j = 0; j < 3; j++) {
            for (int i = t; i < N_PTS; i += 1024) {
                int lv = lab[i];
                int l2 = lab[lv];
                if (l2 < lv) { lab[i] = l2; changed = 1; }
            }
            __syncthreads();
        }

        int c = changed;
        __syncthreads();
        if (!c) break;
    }

    for (int w = t; w < WORDS; w += 1024) bitmap[w] = 0u;
    __syncthreads();
    for (int i = t; i < N_PTS; i += 1024)
        if (lab[i] == i) atomicOr(&bitmap[i >> 5], 1u << (i & 31));
    __syncthreads();

    if (t == 0) {
        int s = 0;
        for (int w = 0; w < WORDS; w++) { wpref[w] = s; s += __popc(bitmap[w]); }
    }
    __syncthreads();

    for (int i = t; i < N_PTS; i += 1024) {
        int lv = lab[i];
        int rank = wpref[lv >> 5] + __popc(bitmap[lv >> 5] & ((1u << (lv & 31)) - 1u));
        out[i] = (float)rank;
    }
}

extern "C" void kernel_launch(void* const* d_in, const int* in_sizes, int n_in,
                              void* d_out, int out_size) {
    const float* x = (const float*)d_in[0];
    float* out = (float*)d_out;

    const int cc_smem = (N_PTS + SM_EDGES) * sizeof(int);        // ~167 KB
    cudaFuncSetAttribute(pair_edges_kernel,
                         cudaFuncAttributeMaxDynamicSharedMemorySize, SM_PAIR_TOTAL);
    cudaFuncSetAttribute(cc_kernel,
                         cudaFuncAttributeMaxDynamicSharedMemorySize, cc_smem);

    norm_init_kernel<<<(N_PTS + 31) / 32, 256>>>(x);

    pair_edges_kernel<<<NTRI, 256, SM_PAIR_TOTAL>>>();

    cc_kernel<<<1, 1024, cc_smem>>>(out);
}